// round 16
// baseline (speedup 1.0000x reference)
#include <cuda_runtime.h>
#include <cuda_fp16.h>
#include <cstdint>

// GumbelSoftmaxVectorQuantizer — round 16
//   Idle GEMM CTAs (bm >= Mp after compaction) zero the padded-row outputs
//   (probs=0, quant=0, ids=-1) concurrently with the MMA-bound compute.
//   Softmax padded blocks become a 1-load early exit.

static constexpr int Mx = 16384;
static constexpr int Kx = 1024;
static constexpr int Nx = 4096;
static constexpr int Vx = 1024;
static constexpr int Dx = 128;
static constexpr float INV_TAU = 0.5f;
static constexpr float FIX_THRESH = 3e-3f;

__device__ float g_logits[(size_t)Mx * Nx];             // by ORIGINAL row
__device__ unsigned short g_Ac[(size_t)Mx * Kx];        // fp16 compact A
__device__ unsigned short g_Bh[(size_t)Nx * Kx];        // fp16 [N][K] = W^T
__device__ unsigned long long g_stats[(size_t)Mx * 4];  // by original row
__device__ int g_cidx[Mx];                              // row -> compact or -1
__device__ int g_rowmap[Mx];                            // compact -> row
__device__ int g_padmap[Mx];                            // pad slot -> row
__device__ int g_Mp;                                    // # nonpad rows

__device__ __forceinline__ uint32_t smem_u32(const void* p) {
    uint32_t a;
    asm("{ .reg .u64 t; cvta.to.shared.u64 t, %1; cvt.u32.u64 %0, t; }" : "=r"(a) : "l"(p));
    return a;
}
__device__ __forceinline__ uint32_t ford(float f) {
    uint32_t b = __float_as_uint(f);
    return (b & 0x80000000u) ? ~b : (b | 0x80000000u);
}
__device__ __forceinline__ float funord(uint32_t u) {
    return __uint_as_float((u & 0x80000000u) ? (u ^ 0x80000000u) : ~u);
}

// ---------------- K-1: scan (1 block, 512 threads) ----------------
__global__ __launch_bounds__(512)
void scan_kernel(const int* __restrict__ pads) {
    __shared__ int part[512];
    const int t = threadIdx.x;
    int flags[32];
    int cnt = 0;
#pragma unroll
    for (int i = 0; i < 32; i++) {
        flags[i] = (pads[t * 32 + i] == 0) ? 1 : 0;
        cnt += flags[i];
    }
    part[t] = cnt;
    __syncthreads();
    for (int off = 1; off < 512; off <<= 1) {
        const int mine = part[t];
        const int other = (t >= off) ? part[t - off] : 0;
        __syncthreads();
        part[t] = mine + other;
        __syncthreads();
    }
    int base  = part[t] - cnt;            // exclusive nonpad
    int pbase = t * 32 - base;            // exclusive pad
#pragma unroll
    for (int i = 0; i < 32; i++) {
        const int row = t * 32 + i;
        if (flags[i]) { g_cidx[row] = base; g_rowmap[base] = row; base++; }
        else          { g_cidx[row] = -1; g_padmap[pbase] = row; pbase++; }
    }
    const int total = part[511];
    if (t == 0) g_Mp = total;
    // zero-fill compact-A tail to next multiple of 128 rows
    const int padto = (total + 127) & ~127;
    const uint4 z = make_uint4(0u, 0u, 0u, 0u);
    for (int r = total + t; r < padto; r += 512) {
        uint4* dst = (uint4*)&g_Ac[(size_t)r << 10];
#pragma unroll
        for (int q = 0; q < 128; q++) dst[q] = z;
    }
}

// ---------------- K0: prep ----------------
__global__ __launch_bounds__(256)
void prep_kernel(const float* __restrict__ A, const float* __restrict__ W) {
    const int bid = blockIdx.x;
    const int tid = threadIdx.x;
    if (bid < 8192) {
        const size_t idx = ((size_t)bid * 256 + tid) * 8;
        const int row = (int)(idx >> 10);
        const int c = g_cidx[row];
        if (c < 0) return;
        float4 a0 = *(const float4*)&A[idx];
        float4 a1 = *(const float4*)&A[idx + 4];
        float v[8] = {a0.x, a0.y, a0.z, a0.w, a1.x, a1.y, a1.z, a1.w};
        unsigned short h[8];
#pragma unroll
        for (int t2 = 0; t2 < 8; t2++)
            h[t2] = __half_as_ushort(__float2half_rn(v[t2]));
        uint4 uh;
        uh.x = h[0] | ((uint32_t)h[1] << 16); uh.y = h[2] | ((uint32_t)h[3] << 16);
        uh.z = h[4] | ((uint32_t)h[5] << 16); uh.w = h[6] | ((uint32_t)h[7] << 16);
        *(uint4*)&g_Ac[((size_t)c << 10) + (idx & 1023)] = uh;
    } else if (bid < 8192 + 1024) {
        __shared__ float s[64][65];
        const int q  = bid - 8192;
        const int ct = q >> 6;
        const int n0 = (q & 63) << 6;
        const int k0 = ct * 64;
        for (int i = tid; i < 1024; i += 256) {
            const int kk = i >> 4, n4 = (i & 15) << 2;
            float4 w = *(const float4*)&W[(size_t)(k0 + kk) * Nx + n0 + n4];
            s[kk][n4] = w.x; s[kk][n4 + 1] = w.y; s[kk][n4 + 2] = w.z; s[kk][n4 + 3] = w.w;
        }
        __syncthreads();
        for (int i = tid; i < 512; i += 256) {
            const int nl = i >> 3, j = (i & 7) << 3;
            unsigned short h[8];
#pragma unroll
            for (int t2 = 0; t2 < 8; t2++)
                h[t2] = __half_as_ushort(__float2half_rn(s[j + t2][nl]));
            const size_t o = (size_t)(n0 + nl) * Kx + k0 + j;
            uint4 uh;
            uh.x = h[0] | ((uint32_t)h[1] << 16); uh.y = h[2] | ((uint32_t)h[3] << 16);
            uh.z = h[4] | ((uint32_t)h[5] << 16); uh.w = h[6] | ((uint32_t)h[7] << 16);
            *(uint4*)&g_Bh[o] = uh;
        }
    } else {
        const size_t base = (size_t)(bid - 9216) * 1024 + tid * 4;
#pragma unroll
        for (int t2 = 0; t2 < 4; t2++) g_stats[base + t2] = 0ull;
    }
}

// ---------------- K1: GEMM + padded-output zeroing on idle CTAs ----------------
static constexpr int BK = 64;
static constexpr int STAGES = 3;
static constexpr int RSTRIDE = 72;
static constexpr int ROW_B = 128;
static constexpr int STAGE_BYTES = 192 * RSTRIDE * 2;
static constexpr int SMEM_BYTES = STAGES * STAGE_BYTES;
static constexpr int NCHUNK = Kx / BK;
static constexpr int NTHREADS = 256;

__device__ __forceinline__ void cp16(uint32_t dst, const void* src) {
    asm volatile("cp.async.cg.shared.global [%0], [%1], 16;" :: "r"(dst), "l"(src) : "memory");
}
__device__ __forceinline__ void cp_commit() {
    asm volatile("cp.async.commit_group;" ::: "memory");
}
__device__ __forceinline__ void cp_wait1() {
    asm volatile("cp.async.wait_group 1;" ::: "memory");
}
__device__ __forceinline__ void ldsm4(uint32_t& r0, uint32_t& r1, uint32_t& r2, uint32_t& r3,
                                      uint32_t addr) {
    asm volatile("ldmatrix.sync.aligned.m8n8.x4.shared.b16 {%0,%1,%2,%3}, [%4];"
                 : "=r"(r0), "=r"(r1), "=r"(r2), "=r"(r3) : "r"(addr));
}
__device__ __forceinline__ void mma_f16(float* c, const uint32_t* a, const uint32_t* b) {
    asm volatile(
        "mma.sync.aligned.m16n8k16.row.col.f32.f16.f16.f32 "
        "{%0,%1,%2,%3}, {%4,%5,%6,%7}, {%8,%9}, {%0,%1,%2,%3};"
        : "+f"(c[0]), "+f"(c[1]), "+f"(c[2]), "+f"(c[3])
        : "r"(a[0]), "r"(a[1]), "r"(a[2]), "r"(a[3]), "r"(b[0]), "r"(b[1]));
}

__global__ __launch_bounds__(NTHREADS, 2)
void gemm_kernel(const float* __restrict__ bias, const float* __restrict__ gum,
                 float* __restrict__ ids_out, float* __restrict__ quant_out,
                 float* __restrict__ probs_out) {
    const int bm = blockIdx.y * 128;
    const int Mp = g_Mp;
    const int tid = threadIdx.x;

    if (bm >= Mp) {
        // idle CTA: zero padded-row outputs, overlapped with MMA CTAs
        const int yStart = (Mp + 127) >> 7;
        const int T = (128 - yStart) * 64;
        const int t = (blockIdx.y - yStart) * 64 + blockIdx.x;
        const int Pn = Mx - Mp;
        const float4 z = make_float4(0.f, 0.f, 0.f, 0.f);
        for (int p = t; p < Pn; p += T) {
            const int row = g_padmap[p];
            float4* pr = (float4*)(probs_out + (size_t)row * 4096);
#pragma unroll
            for (int i = 0; i < 4; i++) pr[tid + i * 256] = z;
            if (tid < 128) ((float4*)(quant_out + (size_t)row * 512))[tid] = z;
            if (tid < 4) ids_out[row * 4 + tid] = -1.0f;
        }
        return;
    }

    extern __shared__ char smem[];
    const uint32_t sbase = smem_u32(smem);
    const int lane = tid & 31;
    const int wid  = tid >> 5;
    const int wm   = wid >> 1;
    const int wn   = wid & 1;
    const int bn   = blockIdx.x * 64;

    const unsigned short* srcAh = g_Ac + (size_t)bm * Kx;
    const unsigned short* srcBh = g_Bh + (size_t)bn * Kx;

    auto issue_stage = [&](int chunk) {
        const int s = chunk % STAGES;
        const uint32_t stb = sbase + s * STAGE_BYTES;
        const size_t kof = (size_t)chunk * BK;
#pragma unroll
        for (int i = 0; i < 4; i++) {
            const int idx = tid + i * 256;
            const int r = idx >> 3, c = idx & 7;
            cp16(stb + (uint32_t)(r * 144 + c * 16),
                 srcAh + (size_t)r * Kx + kof + c * 8);
        }
#pragma unroll
        for (int i = 4; i < 6; i++) {
            const int idx = tid + i * 256;
            const int r = idx >> 3, c = idx & 7;
            cp16(stb + (uint32_t)(r * 144 + c * 16),
                 srcBh + (size_t)(r - 128) * Kx + kof + c * 8);
        }
        cp_commit();
    };

    float acc[2][4][4];
#pragma unroll
    for (int i = 0; i < 2; i++)
#pragma unroll
        for (int j = 0; j < 4; j++)
#pragma unroll
            for (int q = 0; q < 4; q++) acc[i][j][q] = 0.f;

    issue_stage(0); issue_stage(1);

    const int lrow = lane & 15;
    const int lcol = (lane >> 4) * 8;

#pragma unroll 1
    for (int ch = 0; ch < NCHUNK; ch++) {
        cp_wait1();
        __syncthreads();
        if (ch + 2 < NCHUNK) issue_stage(ch + 2);

        const uint32_t stb = sbase + (ch % STAGES) * STAGE_BYTES;

#pragma unroll
        for (int ks = 0; ks < 4; ks++) {
            const int kk = ks * 16;
            uint32_t ah[2][4], bh[4][2];
#pragma unroll
            for (int mf = 0; mf < 2; mf++) {
                const int row = wm * 32 + mf * 16 + lrow;
                const uint32_t off = (uint32_t)(row * RSTRIDE + kk + lcol) * 2;
                ldsm4(ah[mf][0], ah[mf][1], ah[mf][2], ah[mf][3], stb + off);
            }
#pragma unroll
            for (int np = 0; np < 2; np++) {
                const int row = ROW_B + wn * 32 + np * 16 + lrow;
                const uint32_t off = (uint32_t)(row * RSTRIDE + kk + lcol) * 2;
                uint32_t r0, r1, r2, r3;
                ldsm4(r0, r1, r2, r3, stb + off);
                bh[2 * np][0] = r0; bh[2 * np][1] = r2;
                bh[2 * np + 1][0] = r1; bh[2 * np + 1][1] = r3;
            }
#pragma unroll
            for (int mf = 0; mf < 2; mf++)
#pragma unroll
                for (int nf = 0; nf < 4; nf++)
                    mma_f16(acc[mf][nf], ah[mf], bh[nf]);
        }
    }

    const int er = lane >> 2;
    const int ec = (lane & 3) * 2;
    const int g4 = bn >> 10;
    const int vbase = (bn & 1023) + wn * 32;

#pragma unroll
    for (int mf = 0; mf < 2; mf++) {
#pragma unroll
        for (int h = 0; h < 2; h++) {
            const int rowc = bm + wm * 32 + mf * 16 + er + h * 8;
            if (rowc >= Mp) continue;
            const int orow = g_rowmap[rowc];

            float vmax = -3.4e38f; int vidx = 0;
#pragma unroll
            for (int nf = 0; nf < 4; nf++) {
                const int col = bn + wn * 32 + nf * 8 + ec;
                const float2 bb = *(const float2*)&bias[col];
                const size_t go = (size_t)orow * Nx + col;
                const float2 g = *(const float2*)&gum[go];
                float2 o;
                o.x = (acc[mf][nf][2 * h]     + bb.x + g.x) * INV_TAU;
                o.y = (acc[mf][nf][2 * h + 1] + bb.y + g.y) * INV_TAU;
                *(float2*)&g_logits[go] = o;
                const int vc = vbase + nf * 8 + ec;
                if (o.x > vmax) { vmax = o.x; vidx = vc; }
                if (o.y > vmax) { vmax = o.y; vidx = vc + 1; }
            }
            unsigned long long key =
                ((unsigned long long)ford(vmax) << 32) | (uint32_t)(~vidx);
#pragma unroll
            for (int sft = 1; sft <= 2; sft <<= 1) {
                unsigned long long ok = __shfl_xor_sync(0xffffffffu, key, sft);
                if (ok > key) key = ok;
            }
            if ((lane & 3) == 0)
                atomicMax(&g_stats[(size_t)orow * 4 + g4], key);
        }
    }
}

// ---------------- K2: softmax (padded blocks exit; zeroing done by GEMM) ----------------
__global__ __launch_bounds__(128)
void softmax_kernel(const int*   __restrict__ pads,
                    const float* __restrict__ codebook,
                    const float* __restrict__ A,
                    const float* __restrict__ W,
                    const float* __restrict__ bias,
                    const float* __restrict__ gum,
                    float*       __restrict__ ids_out,
                    float*       __restrict__ quant_out,
                    float*       __restrict__ probs_out)
{
    const int grp  = blockIdx.x;
    const int row  = grp >> 2;
    const int g    = grp & 3;
    const int tid  = threadIdx.x;
    const int lane = tid & 31;
    const int warp = tid >> 5;

    if (pads[row]) return;   // outputs already zeroed by idle GEMM CTAs

    __shared__ float ssum[4];
    __shared__ float red_s, sbv;
    __shared__ int   scnt, sbi;
    __shared__ int   scand[7];

    const unsigned long long key = g_stats[grp];
    const float gmax = funord((uint32_t)(key >> 32));
    const int   id0  = (int)(~(uint32_t)key) & 1023;

    const float* base = g_logits + (size_t)grp * Vx;
    float v[8];
    *(float4*)&v[0] = *(const float4*)&base[tid * 8];
    *(float4*)&v[4] = *(const float4*)&base[tid * 8 + 4];

    if (tid == 0) scnt = 0;

    int hasOther = 0;
#pragma unroll
    for (int j = 0; j < 8; j++) {
        const int idx = tid * 8 + j;
        hasOther |= ((gmax - v[j] < FIX_THRESH) && (idx != id0)) ? 1 : 0;
    }
    const int nOther = __syncthreads_count(hasOther);

    if (hasOther) {
#pragma unroll
        for (int j = 0; j < 8; j++) {
            const int idx = tid * 8 + j;
            if ((gmax - v[j] < FIX_THRESH) && (idx != id0)) {
                const int p = atomicAdd(&scnt, 1);
                if (p < 7) scand[p] = idx;
            }
        }
    }

    float e[8]; float s = 0.f;
#pragma unroll
    for (int j = 0; j < 8; j++) { e[j] = __expf(v[j] - gmax); s += e[j]; }
#pragma unroll
    for (int off = 16; off > 0; off >>= 1)
        s += __shfl_down_sync(0xffffffffu, s, off);
    if (lane == 0) ssum[warp] = s;
    __syncthreads();
    if (tid == 0) red_s = ssum[0] + ssum[1] + ssum[2] + ssum[3];
    __syncthreads();

    int id = id0;
    if (nOther > 0) {
        const int ncand = (scnt < 7) ? scnt : 7;
        const float* arow = A + (size_t)row * Kx;
#pragma unroll 1
        for (int c = -1; c < ncand; c++) {
            const int vv = (c < 0) ? id0 : scand[c];
            const int col = (g << 10) + vv;
            float part = 0.f;
#pragma unroll
            for (int j = 0; j < 8; j++) {
                const int k = tid * 8 + j;
                part = fmaf(arow[k], W[(size_t)k * Nx + col], part);
            }
#pragma unroll
            for (int off = 16; off > 0; off >>= 1)
                part += __shfl_down_sync(0xffffffffu, part, off);
            if (lane == 0) ssum[warp] = part;
            __syncthreads();
            if (tid == 0) {
                const float tot = ssum[0] + ssum[1] + ssum[2] + ssum[3];
                const float exact = (tot + bias[col] + gum[(size_t)grp * Vx + vv]) * INV_TAU;
                if (c < 0) { sbv = exact; sbi = vv; }
                else if (exact > sbv || (exact == sbv && vv < sbi)) { sbv = exact; sbi = vv; }
            }
            __syncthreads();
        }
        id = sbi;
    }

    const float inv = 1.f / red_s;
    float4 p0, p1;
    p0.x = e[0] * inv; p0.y = e[1] * inv; p0.z = e[2] * inv; p0.w = e[3] * inv;
    p1.x = e[4] * inv; p1.y = e[5] * inv; p1.z = e[6] * inv; p1.w = e[7] * inv;
    *(float4*)&probs_out[(size_t)grp * Vx + tid * 8]     = p0;
    *(float4*)&probs_out[(size_t)grp * Vx + tid * 8 + 4] = p1;

    quant_out[(size_t)row * (4 * Dx) + g * Dx + tid] =
        codebook[(((g << 10) + id) << 7) + tid];
    if (tid == 0) ids_out[grp] = (float)id;
}

// ---------------- launch ----------------
extern "C" void kernel_launch(void* const* d_in, const int* in_sizes, int n_in,
                              void* d_out, int out_size)
{
    const float* inputs = (const float*)d_in[0];
    const int*   pads   = (const int*)  d_in[1];
    const float* gum    = (const float*)d_in[2];
    const float* W      = (const float*)d_in[3];
    const float* bias   = (const float*)d_in[4];
    const float* cb     = (const float*)d_in[5];

    float* out       = (float*)d_out;
    float* ids_out   = out;
    float* quant_out = out + (size_t)Mx * 4;
    float* probs_out = quant_out + (size_t)Mx * 4 * Dx;

    cudaFuncSetAttribute(gemm_kernel, cudaFuncAttributeMaxDynamicSharedMemorySize, SMEM_BYTES);

    scan_kernel<<<1, 512>>>(pads);
    prep_kernel<<<8192 + 1024 + 64, 256>>>(inputs, W);
    dim3 grid(Nx / 64, Mx / 128);
    gemm_kernel<<<grid, NTHREADS, SMEM_BYTES>>>(bias, gum, ids_out, quant_out, probs_out);
    softmax_kernel<<<Mx * 4, 128>>>(pads, cb, inputs, W, bias, gum,
                                    ids_out, quant_out, probs_out);
}